// round 10
// baseline (speedup 1.0000x reference)
#include <cuda_runtime.h>
#include <math.h>

#define NN 50000
#define EE 400000
#define DD 64
#define HH 4
#define CC 64
#define HC 256
#define EDD 16

typedef unsigned long long ull;

// ---------------- static scratch ----------------
__device__ __align__(16) float g_xl[(size_t)NN * HC];
__device__ __align__(16) float g_xr[(size_t)NN * HC];
__device__ __align__(16) float g_mid[(size_t)NN * DD];
__device__ __align__(16) float g_eacsr[(size_t)EE * EDD];
__device__ __align__(16) float g_part[(size_t)NN * HH * CC];  // per (node, head) normalized partial
__device__ int g_cnt[NN];
__device__ int g_cursor[NN];
__device__ int g_rowptr[NN + 1];
__device__ int g_esrc[EE];
__device__ int g_eord[EE];

// ---------------- packed f32x2 helpers ----------------
__device__ __forceinline__ ull pk2(float a, float b) {
    ull r; asm("mov.b64 %0, {%1, %2};" : "=l"(r) : "f"(a), "f"(b)); return r;
}
__device__ __forceinline__ ull dup2(float a) {
    ull r; asm("mov.b64 %0, {%1, %1};" : "=l"(r) : "f"(a)); return r;
}
__device__ __forceinline__ float2 up2(ull v) {
    float2 r; asm("mov.b64 {%0, %1}, %2;" : "=f"(r.x), "=f"(r.y) : "l"(v)); return r;
}
__device__ __forceinline__ ull fma2(ull a, ull b, ull c) {
    ull d; asm("fma.rn.f32x2 %0, %1, %2, %3;" : "=l"(d) : "l"(a), "l"(b), "l"(c)); return d;
}

// ---------------- CSR build ----------------
__global__ void zero_cnt_kernel() {
    int i = blockIdx.x * blockDim.x + threadIdx.x;
    if (i < NN) g_cnt[i] = 0;
}

__global__ void hist_kernel(const int* __restrict__ dst) {
    int e = blockIdx.x * blockDim.x + threadIdx.x;
    if (e < EE) atomicAdd(&g_cnt[dst[e]], 1);
}

__global__ __launch_bounds__(1024) void scan_kernel() {
    __shared__ int wsum[32];
    int t = threadIdx.x;
    int lane = t & 31, wid = t >> 5;
    const int PER = 49;
    int base = t * PER;

    int s = 0;
#pragma unroll 7
    for (int i = 0; i < PER; i++) {
        int idx = base + i;
        if (idx < NN) s += g_cnt[idx];
    }
    int ws = s;
#pragma unroll
    for (int off = 1; off < 32; off <<= 1) {
        int v = __shfl_up_sync(0xffffffffu, ws, off);
        if (lane >= off) ws += v;
    }
    if (lane == 31) wsum[wid] = ws;
    __syncthreads();
    if (wid == 0) {
        int v = wsum[lane];
        int iv = v;
#pragma unroll
        for (int off = 1; off < 32; off <<= 1) {
            int u = __shfl_up_sync(0xffffffffu, iv, off);
            if (lane >= off) iv += u;
        }
        wsum[lane] = iv - v;
    }
    __syncthreads();
    int offset = wsum[wid] + (ws - s);

    int run = offset;
#pragma unroll 7
    for (int i = 0; i < PER; i++) {
        int idx = base + i;
        if (idx < NN) {
            int v = g_cnt[idx];
            g_rowptr[idx] = run;
            g_cursor[idx] = run;
            run += v;
        }
    }
    if (t == 1023) g_rowptr[NN] = run;
}

__global__ void scatter_kernel(const int* __restrict__ src, const int* __restrict__ dst) {
    int e = blockIdx.x * blockDim.x + threadIdx.x;
    if (e < EE) {
        int d = dst[e];
        int pos = atomicAdd(&g_cursor[d], 1);
        g_esrc[pos] = src[e];
        g_eord[pos] = e;
    }
}

__global__ void permute_ea_kernel(const float* __restrict__ ea) {
    int t = blockIdx.x * blockDim.x + threadIdx.x;
    int pos = t >> 2;
    int c4 = t & 3;
    if (pos < EE) {
        int eid = g_eord[pos];
        ((float4*)g_eacsr)[(size_t)pos * 4 + c4] =
            ((const float4*)ea)[(size_t)eid * 4 + c4];
    }
}

// ---------------- node transform: xl = x@Wl+bl, xr = x@Wr+br ----------------
__global__ __launch_bounds__(512) void transform_kernel(
    const float* __restrict__ x,
    const float* __restrict__ Wl, const float* __restrict__ bl,
    const float* __restrict__ Wr, const float* __restrict__ br)
{
    __shared__ __align__(16) float hs[64 * 64];
    const float* xp = x ? x : g_mid;
    int tid = threadIdx.x;
    int j = tid & 255;
    int isR = tid >> 8;
    const float* W = isR ? Wr : Wl;
    float bj = isR ? br[j] : bl[j];
    float* ob = isR ? g_xr : g_xl;
    int n0 = blockIdx.x * 64;

    ull w2[32];
#pragma unroll
    for (int q = 0; q < 32; q++)
        w2[q] = pk2(W[(2 * q) * HC + j], W[(2 * q + 1) * HC + j]);

    const float4* src4 = (const float4*)(xp + (size_t)n0 * DD);
    int limit4 = (NN - n0) * (DD / 4);
    for (int i = tid; i < 1024; i += 512) {
        float4 v = (i < limit4) ? src4[i] : make_float4(0.f, 0.f, 0.f, 0.f);
        ((float4*)hs)[i] = v;
    }
    __syncthreads();

    int nmax = NN - n0; if (nmax > 64) nmax = 64;
    for (int n = 0; n < nmax; n++) {
        const float4* hrow = (const float4*)(hs + n * 64);
        ull a0 = 0, a1 = 0, a2 = 0, a3 = 0;
#pragma unroll
        for (int q = 0; q < 16; q += 2) {
            float4 h0 = hrow[q], h1 = hrow[q + 1];
            a0 = fma2(pk2(h0.x, h0.y), w2[2 * q + 0], a0);
            a1 = fma2(pk2(h0.z, h0.w), w2[2 * q + 1], a1);
            a2 = fma2(pk2(h1.x, h1.y), w2[2 * q + 2], a2);
            a3 = fma2(pk2(h1.z, h1.w), w2[2 * q + 3], a3);
        }
        float2 f0 = up2(a0), f1 = up2(a1), f2 = up2(a2), f3 = up2(a3);
        ob[(size_t)(n0 + n) * HC + j] =
            bj + ((f0.x + f0.y) + (f1.x + f1.y)) + ((f2.x + f2.y) + (f3.x + f3.y));
    }
}

// ---------------- fused GATv2 attention + aggregation (per-head partials) --------
// block = 128 threads = 4 warps; block owns 16 fixed nodes (grid = NN/16 = 3125).
// warp = head (0..3); lane owns 2 channels: cb = head*64 + lane*2.
// ea + esrc staged in 128-edge chunks; per-warp den complete -> no cross-warp sync.
__global__ __launch_bounds__(128) void gat_kernel(
    const float* __restrict__ We, const float* __restrict__ att)
{
    __shared__ __align__(16) float sh_ea[128 * EDD];  // 8KB
    __shared__ int sh_src[128];
    int tid = threadIdx.x;
    int warp = tid >> 5;   // head index
    int lane = tid & 31;
    int cb = warp * CC + lane * 2;

    // We cache: k-pair packed per channel (16 ull = 32 regs)
    ull w0[8], w1[8];
#pragma unroll
    for (int kp = 0; kp < 8; kp++) {
        w0[kp] = pk2(We[(2 * kp) * HC + cb], We[(2 * kp + 1) * HC + cb]);
        w1[kp] = pk2(We[(2 * kp) * HC + cb + 1], We[(2 * kp + 1) * HC + cb + 1]);
    }
    float2 at = *(const float2*)(att + cb);  // att[4][64] flat == channel index

    int n0 = blockIdx.x * 16;
    int eend = g_rowptr[n0 + 16];
    int sbase = 0, send = -1;

    for (int n = n0; n < n0 + 16; n++) {
        int e0 = g_rowptr[n], e1 = g_rowptr[n + 1];
        float2 xr2 = *(const float2*)(g_xr + (size_t)n * HC + cb);

        ull acc = 0;
        float den = 0.f;

        int e = e0;
        while (e < e1) {
            if (e >= send) {
                // restage: all 4 warps reach this at identical (n, e) -> convergent
                __syncthreads();
                sbase = e;
                int cnt = min(128, eend - sbase);
                const float4* ga = ((const float4*)g_eacsr) + (size_t)sbase * 4;
                for (int i = tid; i < cnt * 4; i += 128)
                    ((float4*)sh_ea)[i] = ga[i];
                if (tid < cnt) sh_src[tid] = g_esrc[sbase + tid];
                __syncthreads();
                send = sbase + cnt;
            }
            int lim = min(e1, send);

            for (; e < lim; e++) {
                int s = sh_src[e - sbase];
                float2 xl2 = *(const float2*)(g_xl + (size_t)s * HC + cb);
                const ull* sea = ((const ull*)sh_ea) + ((e - sbase) << 3);

                // ez accumulators carry xl+xr in low half (summed out at the end)
                ull ez0 = pk2(xl2.x + xr2.x, 0.f);
                ull ez1 = pk2(xl2.y + xr2.y, 0.f);
#pragma unroll
                for (int kp = 0; kp < 8; kp++) {
                    ull ea2 = sea[kp];
                    ez0 = fma2(ea2, w0[kp], ez0);
                    ez1 = fma2(ea2, w1[kp], ez1);
                }
                float2 z0 = up2(ez0), z1 = up2(ez1);
                float y0 = z0.x + z0.y;
                float y1 = z1.x + z1.y;
                float l0 = fmaxf(y0, 0.2f * y0);
                float l1 = fmaxf(y1, 0.2f * y1);
                float ap = l0 * at.x;
                ap = fmaf(l1, at.y, ap);
                // reduce over all 32 lanes (64 channels of this head)
                ap += __shfl_xor_sync(0xffffffffu, ap, 1);
                ap += __shfl_xor_sync(0xffffffffu, ap, 2);
                ap += __shfl_xor_sync(0xffffffffu, ap, 4);
                ap += __shfl_xor_sync(0xffffffffu, ap, 8);
                ap += __shfl_xor_sync(0xffffffffu, ap, 16);

                float ex = __expf(ap);  // softmax w/o max-shift: scale-invariant
                den += ex;
                acc = fma2(pk2(xl2.x, xl2.y), dup2(ex), acc);
            }
        }

        // normalize and store this head's partial (all 32 lanes, coalesced)
        float inv = 1.f / (den + 1e-16f);
        float2 a = up2(acc);
        *(float2*)(g_part + ((size_t)n * HH + warp) * CC + lane * 2) =
            make_float2(a.x * inv, a.y * inv);
    }
}

// ---------------- epilogue: head-mean + bias + LN + residual + GELU ---------------
// 16 lanes per node; 256 threads = 16 nodes per block; grid = 3125.
__global__ __launch_bounds__(256) void epilogue_kernel(
    const float* __restrict__ bias,
    const float* __restrict__ lng, const float* __restrict__ lnb,
    const float* __restrict__ residual,
    float* __restrict__ out_ext, int use_ext)
{
    int idx = blockIdx.x * 256 + threadIdx.x;
    int n = idx >> 4;
    int l = idx & 15;
    float* out = use_ext ? out_ext : g_mid;

    const float* pb = g_part + (size_t)n * HH * CC + l * 4;
    float4 p0 = *(const float4*)(pb);
    float4 p1 = *(const float4*)(pb + CC);
    float4 p2 = *(const float4*)(pb + 2 * CC);
    float4 p3 = *(const float4*)(pb + 3 * CC);
    float4 bi = *(const float4*)(bias + l * 4);
    float r0 = 0.25f * ((p0.x + p1.x) + (p2.x + p3.x)) + bi.x;
    float r1 = 0.25f * ((p0.y + p1.y) + (p2.y + p3.y)) + bi.y;
    float r2 = 0.25f * ((p0.z + p1.z) + (p2.z + p3.z)) + bi.z;
    float r3 = 0.25f * ((p0.w + p1.w) + (p2.w + p3.w)) + bi.w;

    float m = r0 + r1 + r2 + r3;
    m += __shfl_xor_sync(0xffffffffu, m, 1);
    m += __shfl_xor_sync(0xffffffffu, m, 2);
    m += __shfl_xor_sync(0xffffffffu, m, 4);
    m += __shfl_xor_sync(0xffffffffu, m, 8);
    m *= (1.f / 64.f);
    float d0 = r0 - m, d1 = r1 - m, d2 = r2 - m, d3 = r3 - m;
    float v = d0 * d0;
    v = fmaf(d1, d1, v); v = fmaf(d2, d2, v); v = fmaf(d3, d3, v);
    v += __shfl_xor_sync(0xffffffffu, v, 1);
    v += __shfl_xor_sync(0xffffffffu, v, 2);
    v += __shfl_xor_sync(0xffffffffu, v, 4);
    v += __shfl_xor_sync(0xffffffffu, v, 8);
    v *= (1.f / 64.f);
    float rstd = rsqrtf(v + 1e-5f);

    float4 lg = *(const float4*)(lng + l * 4);
    float4 lb = *(const float4*)(lnb + l * 4);
    float y0 = d0 * rstd * lg.x + lb.x;
    float y1 = d1 * rstd * lg.y + lb.y;
    float y2 = d2 * rstd * lg.z + lb.z;
    float y3 = d3 * rstd * lg.w + lb.w;
    if (residual) {
        float4 rs = *(const float4*)(residual + (size_t)n * DD + l * 4);
        y0 += rs.x; y1 += rs.y; y2 += rs.z; y3 += rs.w;
    }
    const float ks = 0.70710678118654752f;
    float o0 = 0.5f * y0 * (1.f + erff(y0 * ks));
    float o1 = 0.5f * y1 * (1.f + erff(y1 * ks));
    float o2 = 0.5f * y2 * (1.f + erff(y2 * ks));
    float o3 = 0.5f * y3 * (1.f + erff(y3 * ks));
    *(float4*)(out + (size_t)n * DD + l * 4) = make_float4(o0, o1, o2, o3);
}

// ---------------- launch ----------------
extern "C" void kernel_launch(void* const* d_in, const int* in_sizes, int n_in,
                              void* d_out, int out_size) {
    const float* h      = (const float*)d_in[0];
    const int*   ei     = (const int*)d_in[1];
    const float* ea     = (const float*)d_in[2];
    const float* g1_Wl  = (const float*)d_in[3];
    const float* g1_bl  = (const float*)d_in[4];
    const float* g1_Wr  = (const float*)d_in[5];
    const float* g1_br  = (const float*)d_in[6];
    const float* g1_We  = (const float*)d_in[7];
    const float* g1_att = (const float*)d_in[8];
    const float* g1_bias= (const float*)d_in[9];
    const float* ln1_g  = (const float*)d_in[10];
    const float* ln1_b  = (const float*)d_in[11];
    const float* g2_Wl  = (const float*)d_in[12];
    const float* g2_bl  = (const float*)d_in[13];
    const float* g2_Wr  = (const float*)d_in[14];
    const float* g2_br  = (const float*)d_in[15];
    const float* g2_We  = (const float*)d_in[16];
    const float* g2_att = (const float*)d_in[17];
    const float* g2_bias= (const float*)d_in[18];
    const float* ln2_g  = (const float*)d_in[19];
    const float* ln2_b  = (const float*)d_in[20];
    float* out = (float*)d_out;

    const int* src = ei;
    const int* dst = ei + EE;

    zero_cnt_kernel<<<(NN + 255) / 256, 256>>>();
    hist_kernel<<<(EE + 255) / 256, 256>>>(dst);
    scan_kernel<<<1, 1024>>>();
    scatter_kernel<<<(EE + 255) / 256, 256>>>(src, dst);
    permute_ea_kernel<<<(EE * 4 + 255) / 256, 256>>>(ea);

    // layer 1
    transform_kernel<<<(NN + 63) / 64, 512>>>(h, g1_Wl, g1_bl, g1_Wr, g1_br);
    gat_kernel<<<NN / 16, 128>>>(g1_We, g1_att);
    epilogue_kernel<<<NN * 16 / 256, 256>>>(g1_bias, ln1_g, ln1_b,
                                            nullptr, nullptr, 0);
    // layer 2
    transform_kernel<<<(NN + 63) / 64, 512>>>(nullptr, g2_Wl, g2_bl, g2_Wr, g2_br);
    gat_kernel<<<NN / 16, 128>>>(g2_We, g2_att);
    epilogue_kernel<<<NN * 16 / 256, 256>>>(g2_bias, ln2_g, ln2_b,
                                            h, out, 1);
}

// round 11
// speedup vs baseline: 1.1090x; 1.1090x over previous
#include <cuda_runtime.h>
#include <math.h>

#define NN 50000
#define EE 400000
#define DD 64
#define HH 4
#define CC 64
#define HC 256
#define EDD 16

typedef unsigned long long ull;

// ---------------- static scratch ----------------
__device__ __align__(16) float g_xl[(size_t)NN * HC];
__device__ __align__(16) float g_xr[(size_t)NN * HC];
__device__ __align__(16) float g_mid[(size_t)NN * DD];
__device__ __align__(16) float g_eacsr[(size_t)EE * EDD];
__device__ __align__(16) float g_part[(size_t)NN * 2 * CC];
__device__ int g_cnt[NN];
__device__ int g_cursor[NN];
__device__ int g_rowptr[NN + 1];
__device__ int g_esrc[EE];
__device__ int g_eord[EE];

// ---------------- packed f32x2 helpers ----------------
__device__ __forceinline__ ull pk2(float a, float b) {
    ull r; asm("mov.b64 %0, {%1, %2};" : "=l"(r) : "f"(a), "f"(b)); return r;
}
__device__ __forceinline__ ull dup2(float a) {
    ull r; asm("mov.b64 %0, {%1, %1};" : "=l"(r) : "f"(a)); return r;
}
__device__ __forceinline__ float2 up2(ull v) {
    float2 r; asm("mov.b64 {%0, %1}, %2;" : "=f"(r.x), "=f"(r.y) : "l"(v)); return r;
}
__device__ __forceinline__ ull fma2(ull a, ull b, ull c) {
    ull d; asm("fma.rn.f32x2 %0, %1, %2, %3;" : "=l"(d) : "l"(a), "l"(b), "l"(c)); return d;
}

// ---------------- CSR build ----------------
__global__ void zero_cnt_kernel() {
    int i = blockIdx.x * blockDim.x + threadIdx.x;
    if (i < NN) g_cnt[i] = 0;
}

__global__ void hist_kernel(const int* __restrict__ dst) {
    int e = blockIdx.x * blockDim.x + threadIdx.x;
    if (e < EE) atomicAdd(&g_cnt[dst[e]], 1);
}

__global__ __launch_bounds__(1024) void scan_kernel() {
    __shared__ int wsum[32];
    int t = threadIdx.x;
    int lane = t & 31, wid = t >> 5;
    const int PER = 49;
    int base = t * PER;

    int s = 0;
#pragma unroll 7
    for (int i = 0; i < PER; i++) {
        int idx = base + i;
        if (idx < NN) s += g_cnt[idx];
    }
    int ws = s;
#pragma unroll
    for (int off = 1; off < 32; off <<= 1) {
        int v = __shfl_up_sync(0xffffffffu, ws, off);
        if (lane >= off) ws += v;
    }
    if (lane == 31) wsum[wid] = ws;
    __syncthreads();
    if (wid == 0) {
        int v = wsum[lane];
        int iv = v;
#pragma unroll
        for (int off = 1; off < 32; off <<= 1) {
            int u = __shfl_up_sync(0xffffffffu, iv, off);
            if (lane >= off) iv += u;
        }
        wsum[lane] = iv - v;
    }
    __syncthreads();
    int offset = wsum[wid] + (ws - s);

    int run = offset;
#pragma unroll 7
    for (int i = 0; i < PER; i++) {
        int idx = base + i;
        if (idx < NN) {
            int v = g_cnt[idx];
            g_rowptr[idx] = run;
            g_cursor[idx] = run;
            run += v;
        }
    }
    if (t == 1023) g_rowptr[NN] = run;
}

__global__ void scatter_kernel(const int* __restrict__ src, const int* __restrict__ dst) {
    int e = blockIdx.x * blockDim.x + threadIdx.x;
    if (e < EE) {
        int d = dst[e];
        int pos = atomicAdd(&g_cursor[d], 1);
        g_esrc[pos] = src[e];
        g_eord[pos] = e;
    }
}

__global__ void permute_ea_kernel(const float* __restrict__ ea) {
    int t = blockIdx.x * blockDim.x + threadIdx.x;
    int pos = t >> 2;
    int c4 = t & 3;
    if (pos < EE) {
        int eid = g_eord[pos];
        ((float4*)g_eacsr)[(size_t)pos * 4 + c4] =
            ((const float4*)ea)[(size_t)eid * 4 + c4];
    }
}

// ---------------- node transform: xl = x@Wl+bl, xr = x@Wr+br ----------------
__global__ __launch_bounds__(512) void transform_kernel(
    const float* __restrict__ x,
    const float* __restrict__ Wl, const float* __restrict__ bl,
    const float* __restrict__ Wr, const float* __restrict__ br)
{
    __shared__ __align__(16) float hs[64 * 64];
    const float* xp = x ? x : g_mid;
    int tid = threadIdx.x;
    int j = tid & 255;
    int isR = tid >> 8;
    const float* W = isR ? Wr : Wl;
    float bj = isR ? br[j] : bl[j];
    float* ob = isR ? g_xr : g_xl;
    int n0 = blockIdx.x * 64;

    ull w2[32];
#pragma unroll
    for (int q = 0; q < 32; q++)
        w2[q] = pk2(W[(2 * q) * HC + j], W[(2 * q + 1) * HC + j]);

    const float4* src4 = (const float4*)(xp + (size_t)n0 * DD);
    int limit4 = (NN - n0) * (DD / 4);
    for (int i = tid; i < 1024; i += 512) {
        float4 v = (i < limit4) ? src4[i] : make_float4(0.f, 0.f, 0.f, 0.f);
        ((float4*)hs)[i] = v;
    }
    __syncthreads();

    int nmax = NN - n0; if (nmax > 64) nmax = 64;
    for (int n = 0; n < nmax; n++) {
        const float4* hrow = (const float4*)(hs + n * 64);
        ull a0 = 0, a1 = 0, a2 = 0, a3 = 0;
#pragma unroll
        for (int q = 0; q < 16; q += 2) {
            float4 h0 = hrow[q], h1 = hrow[q + 1];
            a0 = fma2(pk2(h0.x, h0.y), w2[2 * q + 0], a0);
            a1 = fma2(pk2(h0.z, h0.w), w2[2 * q + 1], a1);
            a2 = fma2(pk2(h1.x, h1.y), w2[2 * q + 2], a2);
            a3 = fma2(pk2(h1.z, h1.w), w2[2 * q + 3], a3);
        }
        float2 f0 = up2(a0), f1 = up2(a1), f2 = up2(a2), f3 = up2(a3);
        ob[(size_t)(n0 + n) * HC + j] =
            bj + ((f0.x + f0.y) + (f1.x + f1.y)) + ((f2.x + f2.y) + (f3.x + f3.y));
    }
}

// per-edge partial attention logit (this lane's 4 channels); ea via LDS.128
__device__ __forceinline__ float edge_ap(
    const ull* __restrict__ w0, const ull* __restrict__ w1,
    const ull* __restrict__ w2r, const ull* __restrict__ w3,
    float4 attv, float4 xl4, float4 xr4, const ulonglong2* __restrict__ sea2)
{
    ull ez0 = 0, ez1 = 0, ez2 = 0, ez3 = 0;
#pragma unroll
    for (int q = 0; q < 4; q++) {
        ulonglong2 v = sea2[q];   // 16B shared load, uniform address -> broadcast
        ez0 = fma2(v.x, w0[2 * q], ez0);
        ez1 = fma2(v.x, w1[2 * q], ez1);
        ez2 = fma2(v.x, w2r[2 * q], ez2);
        ez3 = fma2(v.x, w3[2 * q], ez3);
        ez0 = fma2(v.y, w0[2 * q + 1], ez0);
        ez1 = fma2(v.y, w1[2 * q + 1], ez1);
        ez2 = fma2(v.y, w2r[2 * q + 1], ez2);
        ez3 = fma2(v.y, w3[2 * q + 1], ez3);
    }
    float2 z0 = up2(ez0), z1 = up2(ez1), z2 = up2(ez2), z3 = up2(ez3);
    float y0 = xl4.x + xr4.x + (z0.x + z0.y);
    float y1 = xl4.y + xr4.y + (z1.x + z1.y);
    float y2 = xl4.z + xr4.z + (z2.x + z2.y);
    float y3 = xl4.w + xr4.w + (z3.x + z3.y);
    float l0 = fmaxf(y0, 0.2f * y0);
    float l1 = fmaxf(y1, 0.2f * y1);
    float l2 = fmaxf(y2, 0.2f * y2);
    float l3 = fmaxf(y3, 0.2f * y3);
    float ap = l0 * attv.x;
    ap = fmaf(l1, attv.y, ap);
    ap = fmaf(l2, attv.z, ap);
    ap = fmaf(l3, attv.w, ap);
    return ap;
}

// ---------------- fused GATv2 attention + aggregation (partials only) -----------
// R8 champion structure: block = 64 threads = 2 warps; block owns 8 fixed nodes.
__global__ __launch_bounds__(64) void gat_kernel(
    const float* __restrict__ We, const float* __restrict__ att)
{
    __shared__ __align__(16) float sh_ea[128 * EDD];  // 8KB
    int tid = threadIdx.x;
    int warp = tid >> 5;
    int lane = tid & 31;
    int head = warp * 2 + (lane >> 4);
    int hcb = (lane & 15) * 4;
    int cb = head * CC + hcb;

    // We cache: k-pair packed (64 regs)
    ull w0[8], w1[8], w2r[8], w3[8];
#pragma unroll
    for (int kp = 0; kp < 8; kp++) {
        float4 wa = *(const float4*)(We + (2 * kp) * HC + cb);
        float4 wb = *(const float4*)(We + (2 * kp + 1) * HC + cb);
        w0[kp] = pk2(wa.x, wb.x);
        w1[kp] = pk2(wa.y, wb.y);
        w2r[kp] = pk2(wa.z, wb.z);
        w3[kp] = pk2(wa.w, wb.w);
    }
    float4 attv = *(const float4*)(att + cb);

    int n0 = blockIdx.x * 8;
    int eend = g_rowptr[n0 + 8];
    int sbase = 0, send = -1;

    for (int n = n0; n < n0 + 8; n++) {
        int e0 = g_rowptr[n], e1 = g_rowptr[n + 1];
        float4 xr4 = *(const float4*)(g_xr + (size_t)n * HC + cb);

        ull acc0 = 0, acc1 = 0;
        float den = 0.f;

        int e = e0;
        while (e < e1) {
            if (e >= send) {
                // restage: both warps reach this at identical (n, e) -> convergent
                __syncthreads();
                sbase = e;
                int cnt = min(128, eend - sbase);
                const float4* ga = ((const float4*)g_eacsr) + (size_t)sbase * 4;
                for (int i = tid; i < cnt * 4; i += 64)
                    ((float4*)sh_ea)[i] = ga[i];
                __syncthreads();
                send = sbase + cnt;
            }
            int lim = min(e1, send);

            for (; e + 2 <= lim; e += 2) {
                int sA = g_esrc[e], sB = g_esrc[e + 1];
                float4 xlA = *(const float4*)(g_xl + (size_t)sA * HC + cb);
                float4 xlB = *(const float4*)(g_xl + (size_t)sB * HC + cb);
                const ulonglong2* seaA = ((const ulonglong2*)sh_ea) + ((e - sbase) << 2);
                const ulonglong2* seaB = seaA + 4;

                float apA = edge_ap(w0, w1, w2r, w3, attv, xlA, xr4, seaA);
                float apB = edge_ap(w0, w1, w2r, w3, attv, xlB, xr4, seaB);

                apA += __shfl_xor_sync(0xffffffffu, apA, 1);
                apB += __shfl_xor_sync(0xffffffffu, apB, 1);
                apA += __shfl_xor_sync(0xffffffffu, apA, 2);
                apB += __shfl_xor_sync(0xffffffffu, apB, 2);
                apA += __shfl_xor_sync(0xffffffffu, apA, 4);
                apB += __shfl_xor_sync(0xffffffffu, apB, 4);
                apA += __shfl_xor_sync(0xffffffffu, apA, 8);
                apB += __shfl_xor_sync(0xffffffffu, apB, 8);

                float exA = __expf(apA);  // softmax w/o max-shift: scale-invariant
                float exB = __expf(apB);
                den += exA + exB;
                ull eA = dup2(exA), eB = dup2(exB);
                acc0 = fma2(pk2(xlA.x, xlA.y), eA, acc0);
                acc1 = fma2(pk2(xlA.z, xlA.w), eA, acc1);
                acc0 = fma2(pk2(xlB.x, xlB.y), eB, acc0);
                acc1 = fma2(pk2(xlB.z, xlB.w), eB, acc1);
            }
            if (e < lim) {
                int sA = g_esrc[e];
                float4 xlA = *(const float4*)(g_xl + (size_t)sA * HC + cb);
                const ulonglong2* seaA = ((const ulonglong2*)sh_ea) + ((e - sbase) << 2);
                float ap = edge_ap(w0, w1, w2r, w3, attv, xlA, xr4, seaA);
                ap += __shfl_xor_sync(0xffffffffu, ap, 1);
                ap += __shfl_xor_sync(0xffffffffu, ap, 2);
                ap += __shfl_xor_sync(0xffffffffu, ap, 4);
                ap += __shfl_xor_sync(0xffffffffu, ap, 8);
                float ex = __expf(ap);
                den += ex;
                ull eA = dup2(ex);
                acc0 = fma2(pk2(xlA.x, xlA.y), eA, acc0);
                acc1 = fma2(pk2(xlA.z, xlA.w), eA, acc1);
                e++;
            }
        }

        // normalize per head, combine the warp's two heads, store pair partial
        float inv = 1.f / (den + 1e-16f);
        float2 a0 = up2(acc0), a1 = up2(acc1);
        float r0 = a0.x * inv, r1 = a0.y * inv, r2 = a1.x * inv, r3 = a1.y * inv;

        r0 += __shfl_xor_sync(0xffffffffu, r0, 16);
        r1 += __shfl_xor_sync(0xffffffffu, r1, 16);
        r2 += __shfl_xor_sync(0xffffffffu, r2, 16);
        r3 += __shfl_xor_sync(0xffffffffu, r3, 16);

        if (lane < 16)
            *(float4*)(g_part + ((size_t)n * 2 + warp) * CC + lane * 4) =
                make_float4(r0, r1, r2, r3);
    }
}

// ---------------- epilogue: head-mean + bias + LN + residual + GELU ---------------
__global__ __launch_bounds__(256) void epilogue_kernel(
    const float* __restrict__ bias,
    const float* __restrict__ lng, const float* __restrict__ lnb,
    const float* __restrict__ residual,
    float* __restrict__ out_ext, int use_ext)
{
    int idx = blockIdx.x * 256 + threadIdx.x;
    int n = idx >> 4;
    int l = idx & 15;
    float* out = use_ext ? out_ext : g_mid;

    float4 p0 = *(const float4*)(g_part + (size_t)n * 2 * CC + l * 4);
    float4 p1 = *(const float4*)(g_part + ((size_t)n * 2 + 1) * CC + l * 4);
    float4 bi = *(const float4*)(bias + l * 4);
    float r0 = 0.25f * (p0.x + p1.x) + bi.x;
    float r1 = 0.25f * (p0.y + p1.y) + bi.y;
    float r2 = 0.25f * (p0.z + p1.z) + bi.z;
    float r3 = 0.25f * (p0.w + p1.w) + bi.w;

    float m = r0 + r1 + r2 + r3;
    m += __shfl_xor_sync(0xffffffffu, m, 1);
    m += __shfl_xor_sync(0xffffffffu, m, 2);
    m += __shfl_xor_sync(0xffffffffu, m, 4);
    m += __shfl_xor_sync(0xffffffffu, m, 8);
    m *= (1.f / 64.f);
    float d0 = r0 - m, d1 = r1 - m, d2 = r2 - m, d3 = r3 - m;
    float v = d0 * d0;
    v = fmaf(d1, d1, v); v = fmaf(d2, d2, v); v = fmaf(d3, d3, v);
    v += __shfl_xor_sync(0xffffffffu, v, 1);
    v += __shfl_xor_sync(0xffffffffu, v, 2);
    v += __shfl_xor_sync(0xffffffffu, v, 4);
    v += __shfl_xor_sync(0xffffffffu, v, 8);
    v *= (1.f / 64.f);
    float rstd = rsqrtf(v + 1e-5f);

    float4 lg = *(const float4*)(lng + l * 4);
    float4 lb = *(const float4*)(lnb + l * 4);
    float y0 = d0 * rstd * lg.x + lb.x;
    float y1 = d1 * rstd * lg.y + lb.y;
    float y2 = d2 * rstd * lg.z + lb.z;
    float y3 = d3 * rstd * lg.w + lb.w;
    if (residual) {
        float4 rs = *(const float4*)(residual + (size_t)n * DD + l * 4);
        y0 += rs.x; y1 += rs.y; y2 += rs.z; y3 += rs.w;
    }
    const float ks = 0.70710678118654752f;
    float o0 = 0.5f * y0 * (1.f + erff(y0 * ks));
    float o1 = 0.5f * y1 * (1.f + erff(y1 * ks));
    float o2 = 0.5f * y2 * (1.f + erff(y2 * ks));
    float o3 = 0.5f * y3 * (1.f + erff(y3 * ks));
    *(float4*)(out + (size_t)n * DD + l * 4) = make_float4(o0, o1, o2, o3);
}

// ---------------- launch ----------------
extern "C" void kernel_launch(void* const* d_in, const int* in_sizes, int n_in,
                              void* d_out, int out_size) {
    const float* h      = (const float*)d_in[0];
    const int*   ei     = (const int*)d_in[1];
    const float* ea     = (const float*)d_in[2];
    const float* g1_Wl  = (const float*)d_in[3];
    const float* g1_bl  = (const float*)d_in[4];
    const float* g1_Wr  = (const float*)d_in[5];
    const float* g1_br  = (const float*)d_in[6];
    const float* g1_We  = (const float*)d_in[7];
    const float* g1_att = (const float*)d_in[8];
    const float* g1_bias= (const float*)d_in[9];
    const float* ln1_g  = (const float*)d_in[10];
    const float* ln1_b  = (const float*)d_in[11];
    const float* g2_Wl  = (const float*)d_in[12];
    const float* g2_bl  = (const float*)d_in[13];
    const float* g2_Wr  = (const float*)d_in[14];
    const float* g2_br  = (const float*)d_in[15];
    const float* g2_We  = (const float*)d_in[16];
    const float* g2_att = (const float*)d_in[17];
    const float* g2_bias= (const float*)d_in[18];
    const float* ln2_g  = (const float*)d_in[19];
    const float* ln2_b  = (const float*)d_in[20];
    float* out = (float*)d_out;

    const int* src = ei;
    const int* dst = ei + EE;

    // Fork a side stream: CSR build runs concurrently with transform1 (independent).
    cudaStream_t s2;
    cudaStreamCreateWithFlags(&s2, cudaStreamNonBlocking);
    cudaEvent_t evFork, evJoin;
    cudaEventCreateWithFlags(&evFork, cudaEventDisableTiming);
    cudaEventCreateWithFlags(&evJoin, cudaEventDisableTiming);

    cudaEventRecord(evFork, 0);
    cudaStreamWaitEvent(s2, evFork, 0);

    // CSR chain on side stream
    zero_cnt_kernel<<<(NN + 255) / 256, 256, 0, s2>>>();
    hist_kernel<<<(EE + 255) / 256, 256, 0, s2>>>(dst);
    scan_kernel<<<1, 1024, 0, s2>>>();
    scatter_kernel<<<(EE + 255) / 256, 256, 0, s2>>>(src, dst);
    permute_ea_kernel<<<(EE * 4 + 255) / 256, 256, 0, s2>>>(ea);
    cudaEventRecord(evJoin, s2);

    // transform1 on main stream, concurrent with CSR chain
    transform_kernel<<<(NN + 63) / 64, 512>>>(h, g1_Wl, g1_bl, g1_Wr, g1_br);

    // join: gat needs both CSR and transform1
    cudaStreamWaitEvent(0, evJoin, 0);

    gat_kernel<<<NN / 8, 64>>>(g1_We, g1_att);
    epilogue_kernel<<<NN * 16 / 256, 256>>>(g1_bias, ln1_g, ln1_b,
                                            nullptr, nullptr, 0);
    // layer 2
    transform_kernel<<<(NN + 63) / 64, 512>>>(nullptr, g2_Wl, g2_bl, g2_Wr, g2_br);
    gat_kernel<<<NN / 8, 64>>>(g2_We, g2_att);
    epilogue_kernel<<<NN * 16 / 256, 256>>>(g2_bias, ln2_g, ln2_b,
                                            h, out, 1);

    cudaEventDestroy(evFork);
    cudaEventDestroy(evJoin);
    cudaStreamDestroy(s2);
}